// round 1
// baseline (speedup 1.0000x reference)
#include <cuda_runtime.h>
#include <cstdint>

// Problem shape (fixed by reference):
//   x1: [2048, 4096] fp32, x2: [4096, 4096] fp32
//   out = tile(x1 @ x2, (1, 30)) -> [2048, 122880] fp32
#define MDIM 2048
#define NDIM 4096
#define KDIM 4096
#define NREP 30
#define OUTN (NDIM * NREP)   // 122880

#define BM 128
#define BN 128
#define BK 16
#define SPAD 132             // padded smem row stride (floats): k*132+m -> unique banks for frag loads

__device__ __forceinline__ uint32_t f2tf32(float x) {
    uint32_t y;
    asm("cvt.rna.tf32.f32 %0, %1;" : "=r"(y) : "f"(x));
    return y;
}

__global__ __launch_bounds__(256)
void Model_82454782148931_kernel(const float* __restrict__ A,
                                 const float* __restrict__ B,
                                 float* __restrict__ out) {
    __shared__ float As[BK][SPAD];   // As[k][m], tf32-rounded
    __shared__ float Bs[BK][SPAD];   // Bs[k][n], tf32-rounded

    const int tid  = threadIdx.x;
    const int lane = tid & 31;
    const int warp = tid >> 5;
    const int wm   = warp >> 1;      // 0..3 -> 32-row slab
    const int wn   = warp & 1;       // 0..1 -> 64-col slab
    const int bm0  = blockIdx.y * BM;
    const int bn0  = blockIdx.x * BN;

    // Accumulators: warp tile 32x64 = 2 (m16) x 8 (n8) mma tiles
    float c[2][8][4];
    #pragma unroll
    for (int mt = 0; mt < 2; mt++)
        #pragma unroll
        for (int nt = 0; nt < 8; nt++)
            #pragma unroll
            for (int i = 0; i < 4; i++)
                c[mt][nt][i] = 0.0f;

    // Global-load register prefetch (2 float4 for A, 2 for B per thread)
    float4 pa[2], pb[2];
    #pragma unroll
    for (int i = 0; i < 2; i++) {
        const int id  = tid + i * 256;
        const int ar  = id >> 2;          // 0..127
        const int ac4 = id & 3;           // 0..3  (16 floats per A row)
        const int br  = id >> 5;          // 0..15
        const int bc4 = id & 31;          // 0..31 (128 floats per B row)
        pa[i] = *(const float4*)&A[(size_t)(bm0 + ar) * KDIM + ac4 * 4];
        pb[i] = *(const float4*)&B[(size_t)br * NDIM + bn0 + bc4 * 4];
    }

    const int NK = KDIM / BK;  // 256
    for (int kt = 0; kt < NK; kt++) {
        // Commit prefetched tile to smem (with TF32 rounding)
        #pragma unroll
        for (int i = 0; i < 2; i++) {
            const int id  = tid + i * 256;
            const int ar  = id >> 2;
            const int ac  = (id & 3) * 4;
            As[ac + 0][ar] = __uint_as_float(f2tf32(pa[i].x));
            As[ac + 1][ar] = __uint_as_float(f2tf32(pa[i].y));
            As[ac + 2][ar] = __uint_as_float(f2tf32(pa[i].z));
            As[ac + 3][ar] = __uint_as_float(f2tf32(pa[i].w));
            const int br = id >> 5;
            const int bc = (id & 31) * 4;
            float4 v;
            v.x = __uint_as_float(f2tf32(pb[i].x));
            v.y = __uint_as_float(f2tf32(pb[i].y));
            v.z = __uint_as_float(f2tf32(pb[i].z));
            v.w = __uint_as_float(f2tf32(pb[i].w));
            *(float4*)&Bs[br][bc] = v;
        }
        __syncthreads();

        // Issue next tile's global loads early (latency hiding under compute)
        if (kt + 1 < NK) {
            const int kof = (kt + 1) * BK;
            #pragma unroll
            for (int i = 0; i < 2; i++) {
                const int id  = tid + i * 256;
                const int ar  = id >> 2;
                const int ac4 = id & 3;
                const int br  = id >> 5;
                const int bc4 = id & 31;
                pa[i] = *(const float4*)&A[(size_t)(bm0 + ar) * KDIM + kof + ac4 * 4];
                pb[i] = *(const float4*)&B[(size_t)(kof + br) * NDIM + bn0 + bc4 * 4];
            }
        }

        // Compute: 2 k-steps of 8
        #pragma unroll
        for (int ks = 0; ks < 2; ks++) {
            const int k0 = ks * 8;
            const int r  = lane >> 2;     // 0..7
            const int cq = lane & 3;      // 0..3
            uint32_t a[2][4], b[8][2];
            #pragma unroll
            for (int mt = 0; mt < 2; mt++) {
                const int m = wm * 32 + mt * 16 + r;
                a[mt][0] = __float_as_uint(As[k0 + cq][m]);
                a[mt][1] = __float_as_uint(As[k0 + cq][m + 8]);
                a[mt][2] = __float_as_uint(As[k0 + cq + 4][m]);
                a[mt][3] = __float_as_uint(As[k0 + cq + 4][m + 8]);
            }
            #pragma unroll
            for (int nt = 0; nt < 8; nt++) {
                const int n = wn * 64 + nt * 8 + r;
                b[nt][0] = __float_as_uint(Bs[k0 + cq][n]);
                b[nt][1] = __float_as_uint(Bs[k0 + cq + 4][n]);
            }
            #pragma unroll
            for (int mt = 0; mt < 2; mt++)
                #pragma unroll
                for (int nt = 0; nt < 8; nt++) {
                    asm volatile(
                        "mma.sync.aligned.m16n8k8.row.col.f32.tf32.tf32.f32 "
                        "{%0,%1,%2,%3},{%4,%5,%6,%7},{%8,%9},{%0,%1,%2,%3};"
                        : "+f"(c[mt][nt][0]), "+f"(c[mt][nt][1]),
                          "+f"(c[mt][nt][2]), "+f"(c[mt][nt][3])
                        : "r"(a[mt][0]), "r"(a[mt][1]), "r"(a[mt][2]), "r"(a[mt][3]),
                          "r"(b[nt][0]), "r"(b[nt][1]));
                }
        }
        __syncthreads();
    }

    // Fused epilogue: write the C tile at all 30 replica positions.
    // Streaming stores — 1 GB output has zero reuse, don't pollute L2.
    #pragma unroll
    for (int mt = 0; mt < 2; mt++) {
        const int row0 = bm0 + wm * 32 + mt * 16 + (lane >> 2);
        #pragma unroll
        for (int nt = 0; nt < 8; nt++) {
            const int col = bn0 + wn * 64 + nt * 8 + (lane & 3) * 2;
            const float2 v01 = make_float2(c[mt][nt][0], c[mt][nt][1]);
            const float2 v23 = make_float2(c[mt][nt][2], c[mt][nt][3]);
            float* p0 = out + (size_t)row0 * OUTN + col;
            float* p1 = out + (size_t)(row0 + 8) * OUTN + col;
            #pragma unroll
            for (int rep = 0; rep < NREP; rep++) {
                __stcs((float2*)(p0 + (size_t)rep * NDIM), v01);
                __stcs((float2*)(p1 + (size_t)rep * NDIM), v23);
            }
        }
    }
}

extern "C" void kernel_launch(void* const* d_in, const int* in_sizes, int n_in,
                              void* d_out, int out_size) {
    const float* x1 = (const float*)d_in[0];
    const float* x2 = (const float*)d_in[1];
    float* out = (float*)d_out;
    dim3 grid(NDIM / BN, MDIM / BM);   // (32, 16) = 512 blocks
    Model_82454782148931_kernel<<<grid, 256>>>(x1, x2, out);
}

// round 3
// speedup vs baseline: 1.7839x; 1.7839x over previous
#include <cuda_runtime.h>
#include <cstdint>

// out[2048, 122880] = tile(x1[2048,4096] @ x2[4096,4096], 30x), fp32, TF32 mma.sync path.
// Strategy: prepass permutes A/B into mma-fragment order (tf32-rounded) in global
// scratch; GEMM mainloop does only LDS.128 fragment loads (conflict-free) + HMMA;
// epilogue streams 30 replicas straight from registers as full-sector float2 stores.
#define MDIM 2048
#define NDIM 4096
#define KDIM 4096
#define NREP 30
#define OUTN (NDIM * NREP)

#define BM 128
#define BN 128
#define BK 32
#define STAGES 3
#define NKT (KDIM / BK)          // 128
#define STAGE_BYTES 32768        // 16KB A frags + 16KB B frags
#define SMEM_TOTAL (STAGES * STAGE_BYTES)   // 96KB

// Fragment-ordered scratch:
//  g_Af[m16][k8][lane][4] : per-lane A fragment words of one m16n8k8 tile (512B/tile)
//  g_Bf[n16][k8][lane][4] : per-lane B fragment words of TWO adjacent n8 tiles (512B)
__device__ float g_Af[(size_t)MDIM * KDIM];
__device__ float g_Bf[(size_t)NDIM * KDIM];

__device__ __forceinline__ uint32_t f2tf32(float x) {
    uint32_t y;
    asm("cvt.rna.tf32.f32 %0, %1;" : "=r"(y) : "f"(x));
    return y;
}
__device__ __forceinline__ float rtf(float x) { return __uint_as_float(f2tf32(x)); }

__device__ __forceinline__ uint32_t smem_u32(const void* p) {
    uint32_t a;
    asm("{ .reg .u64 t; cvta.to.shared.u64 t, %1; cvt.u32.u64 %0, t; }" : "=r"(a) : "l"(p));
    return a;
}
__device__ __forceinline__ void cp_async16(uint32_t dst, const void* src) {
    asm volatile("cp.async.cg.shared.global [%0], [%1], 16;" :: "r"(dst), "l"(src) : "memory");
}
#define CP_COMMIT() asm volatile("cp.async.commit_group;" ::: "memory")
#define CP_WAIT1()  asm volatile("cp.async.wait_group 1;" ::: "memory")

__device__ __forceinline__ void mma_tf32(float c[4], uint32_t a0, uint32_t a1,
                                         uint32_t a2, uint32_t a3,
                                         uint32_t b0, uint32_t b1) {
    asm volatile(
        "mma.sync.aligned.m16n8k8.row.col.f32.tf32.tf32.f32 "
        "{%0,%1,%2,%3},{%4,%5,%6,%7},{%8,%9},{%0,%1,%2,%3};"
        : "+f"(c[0]), "+f"(c[1]), "+f"(c[2]), "+f"(c[3])
        : "r"(a0), "r"(a1), "r"(a2), "r"(a3), "r"(b0), "r"(b1));
}

// ---------------- prepass A: [M][K] -> fragment order, tf32-rounded ----------------
// grid (K/512, M/16), block 256
__global__ __launch_bounds__(256)
void prepA_kernel(const float* __restrict__ A) {
    __shared__ float sA[16][516];           // pad: conflict-free frag reads
    const int bx = blockIdx.x, m16 = blockIdx.y;
    const int tid = threadIdx.x, lane = tid & 31, warp = tid >> 5;
    #pragma unroll
    for (int i = 0; i < 8; i++) {
        const int idx = i * 256 + tid;      // 2048 float4s
        const int r = idx >> 7, c4 = idx & 127;
        float4 v = *(const float4*)&A[(size_t)(m16 * 16 + r) * KDIM + bx * 512 + c4 * 4];
        v.x = rtf(v.x); v.y = rtf(v.y); v.z = rtf(v.z); v.w = rtf(v.w);
        *(float4*)&sA[r][c4 * 4] = v;
    }
    __syncthreads();
    const int r = lane >> 2, cq = lane & 3;
    #pragma unroll
    for (int t = 0; t < 8; t++) {
        const int k8l = warp * 8 + t;       // 0..63
        float4 w;
        w.x = sA[r][k8l * 8 + cq];
        w.y = sA[r + 8][k8l * 8 + cq];
        w.z = sA[r][k8l * 8 + cq + 4];
        w.w = sA[r + 8][k8l * 8 + cq + 4];
        const size_t o = ((size_t)m16 * 512 + bx * 64 + k8l) * 32 + lane;
        ((float4*)g_Af)[o] = w;
    }
}

// ---------------- prepass B: [K][N] -> fragment order (n16-pair packing) ----------------
// grid (K/128, N/64), block 256
__global__ __launch_bounds__(256)
void prepB_kernel(const float* __restrict__ B) {
    __shared__ float sB[128][68];
    const int bx = blockIdx.x, by = blockIdx.y;
    const int tid = threadIdx.x, lane = tid & 31, warp = tid >> 5;
    #pragma unroll
    for (int i = 0; i < 8; i++) {
        const int idx = i * 256 + tid;      // 2048 float4s
        const int kr = idx >> 4, c4 = idx & 15;
        float4 v = *(const float4*)&B[(size_t)(bx * 128 + kr) * NDIM + by * 64 + c4 * 4];
        v.x = rtf(v.x); v.y = rtf(v.y); v.z = rtf(v.z); v.w = rtf(v.w);
        *(float4*)&sB[kr][c4 * 4] = v;
    }
    __syncthreads();
    const int r = lane >> 2, cq = lane & 3;
    #pragma unroll
    for (int t = 0; t < 8; t++) {
        const int id = warp * 8 + t;        // 64 tiles: 4 n16 x 16 k8
        const int n16l = id >> 4, k8l = id & 15;
        float4 w;
        w.x = sB[k8l * 8 + cq][n16l * 16 + r];
        w.y = sB[k8l * 8 + cq + 4][n16l * 16 + r];
        w.z = sB[k8l * 8 + cq][n16l * 16 + 8 + r];
        w.w = sB[k8l * 8 + cq + 4][n16l * 16 + 8 + r];
        const size_t o = ((size_t)(by * 4 + n16l) * 512 + bx * 16 + k8l) * 32 + lane;
        ((float4*)g_Bf)[o] = w;
    }
}

// ---------------- GEMM: 128x128x32 CTA, 4 warps of 64x64, 3-stage cp.async ----------------
__global__ __launch_bounds__(128, 2)
void Model_82454782148931_gemm(float* __restrict__ out) {
    extern __shared__ char smem[];
    const uint32_t sbase = smem_u32(smem);
    const int tid  = threadIdx.x;
    const int lane = tid & 31;
    const int warp = tid >> 5;
    const int wm   = warp >> 1;             // 0..1
    const int wn   = warp & 1;              // 0..1
    const int bm16 = blockIdx.y * 8;
    const int bn16 = blockIdx.x * 8;

    const float4* Af4 = (const float4*)g_Af;
    const float4* Bf4 = (const float4*)g_Bf;

    float c[4][8][4];
    #pragma unroll
    for (int mt = 0; mt < 4; mt++)
        #pragma unroll
        for (int nt = 0; nt < 8; nt++)
            #pragma unroll
            for (int i = 0; i < 4; i++) c[mt][nt][i] = 0.0f;

    // stage layout: A frags at frag*512 (frag = m16l*4 + k8l), B frags at 16K + frag*512
    auto load_stage = [&](int s, int kt) {
        const uint32_t ab = sbase + s * STAGE_BYTES;
        #pragma unroll
        for (int i = 0; i < 8; i++) {
            const int idx = i * 128 + tid;  // 1024 float4 per operand
            const int m16l = idx >> 7;      // 0..7
            const int k8l  = (idx >> 5) & 3;
            const int ln   = idx & 31;
            cp_async16(ab + idx * 16,
                       Af4 + ((size_t)(bm16 + m16l) * 512 + kt * 4 + k8l) * 32 + ln);
            cp_async16(ab + 16384 + idx * 16,
                       Bf4 + ((size_t)(bn16 + m16l) * 512 + kt * 4 + k8l) * 32 + ln);
        }
    };

    load_stage(0, 0); CP_COMMIT();
    load_stage(1, 1); CP_COMMIT();

    #pragma unroll 1
    for (int kt = 0; kt < NKT; kt++) {
        const int s = kt % STAGES;
        CP_WAIT1();
        __syncthreads();
        if (kt + 2 < NKT) load_stage((kt + 2) % STAGES, kt + 2);
        CP_COMMIT();

        const char* ap = smem + s * STAGE_BYTES + (size_t)(wm * 16) * 512 + lane * 16;
        const char* bp = smem + s * STAGE_BYTES + 16384 + (size_t)(wn * 16) * 512 + lane * 16;
        #pragma unroll
        for (int ks = 0; ks < 4; ks++) {
            uint4 af[4], bf[4];
            #pragma unroll
            for (int mt = 0; mt < 4; mt++)
                af[mt] = *(const uint4*)(ap + (mt * 4 + ks) * 512);
            #pragma unroll
            for (int j = 0; j < 4; j++)
                bf[j] = *(const uint4*)(bp + (j * 4 + ks) * 512);
            #pragma unroll
            for (int mt = 0; mt < 4; mt++)
                #pragma unroll
                for (int j = 0; j < 4; j++) {
                    mma_tf32(c[mt][2 * j],     af[mt].x, af[mt].y, af[mt].z, af[mt].w,
                             bf[j].x, bf[j].y);
                    mma_tf32(c[mt][2 * j + 1], af[mt].x, af[mt].y, af[mt].z, af[mt].w,
                             bf[j].z, bf[j].w);
                }
        }
    }

    // ---- epilogue: 30x replicated streaming stores straight from registers.
    // float2 per (row, 8B): lanes q=0..3 of each row-group form one full 32B sector.
    const int bm0 = blockIdx.y * BM;
    const int bn0 = blockIdx.x * BN;
    #pragma unroll
    for (int mt = 0; mt < 4; mt++) {
        const int row0 = bm0 + wm * 64 + mt * 16 + (lane >> 2);
        #pragma unroll
        for (int nt = 0; nt < 8; nt++) {
            const int col = bn0 + wn * 64 + nt * 8 + (lane & 3) * 2;
            const float2 v01 = make_float2(c[mt][nt][0], c[mt][nt][1]);
            const float2 v23 = make_float2(c[mt][nt][2], c[mt][nt][3]);
            float* p0 = out + (size_t)row0 * OUTN + col;
            float* p1 = p0 + (size_t)8 * OUTN;
            #pragma unroll
            for (int rep = 0; rep < NREP; rep++) {
                __stcs((float2*)(p0 + (size_t)rep * NDIM), v01);
                __stcs((float2*)(p1 + (size_t)rep * NDIM), v23);
            }
        }
    }
}

extern "C" void kernel_launch(void* const* d_in, const int* in_sizes, int n_in,
                              void* d_out, int out_size) {
    const float* x1 = (const float*)d_in[0];
    const float* x2 = (const float*)d_in[1];
    float* out = (float*)d_out;

    prepA_kernel<<<dim3(KDIM / 512, MDIM / 16), 256>>>(x1);
    prepB_kernel<<<dim3(KDIM / 128, NDIM / 64), 256>>>(x2);

    cudaFuncSetAttribute(Model_82454782148931_gemm,
                         cudaFuncAttributeMaxDynamicSharedMemorySize, SMEM_TOTAL);
    dim3 grid(NDIM / BN, MDIM / BM);   // (32, 16)
    Model_82454782148931_gemm<<<grid, 128, SMEM_TOTAL>>>(out);
}